// round 11
// baseline (speedup 1.0000x reference)
#include <cuda_runtime.h>

#define NS    1024
#define XD    128
#define HID   256
#define SPLIT 2
#define KHALF (HID / SPLIT)      // 128

typedef unsigned long long u64;
union F2 { u64 u; float f[2]; };

// Scratch (device globals — no allocation allowed)
__device__ float g_px_t[HID * NS];        // pre_x transposed: [k][j]
__device__ u64   g_pyd[HID * NS];         // (pre_y + b1) transposed, dup (v,v): [k][i]
__device__ u64   g_w2p[HID];              // W2 packed (w,w)
__device__ float g_t1p[SPLIT][NS * NS];   // partial T1 sums (8 MB, L2-resident)
__device__ float g_sum_exp;
__device__ float g_sum_diag;
__device__ unsigned g_done;

__device__ __forceinline__ u64 pack2(float lo, float hi) {
    u64 r; asm("mov.b64 %0, {%1, %2};" : "=l"(r) : "f"(lo), "f"(hi)); return r;
}
__device__ __forceinline__ u64 add2(u64 a, u64 b) {
    u64 r; asm("add.rn.f32x2 %0, %1, %2;" : "=l"(r) : "l"(a), "l"(b)); return r;
}
__device__ __forceinline__ u64 fma2(u64 a, u64 b, u64 c) {
    u64 r; asm("fma.rn.f32x2 %0, %1, %2, %3;" : "=l"(r) : "l"(a), "l"(b), "l"(c)); return r;
}
__device__ __forceinline__ u64 relu2(u64 a) {
    F2 v; v.u = a;
    v.f[0] = fmaxf(v.f[0], 0.0f);
    v.f[1] = fmaxf(v.f[1], 0.0f);
    return v.u;
}
__device__ __forceinline__ void cpa16(void* smem, const void* gmem) {
    unsigned s = (unsigned)__cvta_generic_to_shared(smem);
    asm volatile("cp.async.cg.shared.global [%0], [%1], 16;" :: "r"(s), "l"(gmem));
}
__device__ __forceinline__ void cpa_commit() {
    asm volatile("cp.async.commit_group;");
}
template <int N>
__device__ __forceinline__ void cpa_wait() {
    asm volatile("cp.async.wait_group %0;" :: "n"(N));
}

// ---------------------------------------------------------------------------
// Kernel 1: pre_x / pre_yb transposed; zero accumulators; pack W2.
// grid (HID/64, NS/64, 2), block (16,16). (Proven shape from R7.)
// ---------------------------------------------------------------------------
__global__ void gemm_pre_kernel(const float* __restrict__ x,
                                const float* __restrict__ y,
                                const float* __restrict__ W1,
                                const float* __restrict__ b1,
                                const float* __restrict__ W2) {
    const int bz = blockIdx.z;
    const float* __restrict__ A = bz ? y : x;
    const float* __restrict__ W = W1 + (bz ? (XD * HID) : 0);

    __shared__ float As[16][64];   // [k][n]
    __shared__ float Bs[16][64];   // [k][h]

    const int tx = threadIdx.x, ty = threadIdx.y;
    const int tid = ty * 16 + tx;
    const int n0 = blockIdx.y * 64;
    const int h0 = blockIdx.x * 64;

    if (blockIdx.x == 0 && blockIdx.y == 0 && bz == 0) {
        if (tid == 0) { g_sum_exp = 0.0f; g_sum_diag = 0.0f; }
        float w = W2[tid];                 // 256 threads == HID
        g_w2p[tid] = pack2(w, w);
    }

    u64 acc[4][2];
#pragma unroll
    for (int a = 0; a < 4; a++) { acc[a][0] = 0ull; acc[a][1] = 0ull; }

    for (int kk = 0; kk < XD; kk += 16) {
        {
            int m  = tid >> 2;
            int k4 = (tid & 3) * 4;
            float4 v = *(const float4*)&A[(n0 + m) * XD + kk + k4];
            As[k4 + 0][m] = v.x;
            As[k4 + 1][m] = v.y;
            As[k4 + 2][m] = v.z;
            As[k4 + 3][m] = v.w;
        }
#pragma unroll
        for (int t = 0; t < 4; t++) {
            int e = tid + t * 256;
            int h = e & 63;
            int k = e >> 6;
            Bs[k][h] = W[(kk + k) * HID + h0 + h];
        }
        __syncthreads();

#pragma unroll
        for (int k = 0; k < 16; k++) {
            float4 av = *(const float4*)&As[k][ty * 4];
            ulonglong2 bv = *(const ulonglong2*)&Bs[k][tx * 4];
            float aa[4] = {av.x, av.y, av.z, av.w};
#pragma unroll
            for (int a = 0; a < 4; a++) {
                u64 ap = pack2(aa[a], aa[a]);
                acc[a][0] = fma2(ap, bv.x, acc[a][0]);
                acc[a][1] = fma2(ap, bv.y, acc[a][1]);
            }
        }
        __syncthreads();
    }

    if (bz == 0) {
#pragma unroll
        for (int b = 0; b < 4; b++) {
            int h = h0 + tx * 4 + b;
            F2 p0, p1, p2, p3;
            p0.u = acc[0][b >> 1]; p1.u = acc[1][b >> 1];
            p2.u = acc[2][b >> 1]; p3.u = acc[3][b >> 1];
            int hl = b & 1;
            float4 v = make_float4(p0.f[hl], p1.f[hl], p2.f[hl], p3.f[hl]);
            *(float4*)&g_px_t[h * NS + n0 + ty * 4] = v;
        }
    } else {
#pragma unroll
        for (int b = 0; b < 4; b++) {
            int h = h0 + tx * 4 + b;
            float bias = b1[h];
            int hl = b & 1;
            u64 vals[4];
#pragma unroll
            for (int a = 0; a < 4; a++) {
                F2 p; p.u = acc[a][b >> 1];
                float v = p.f[hl] + bias;
                vals[a] = pack2(v, v);
            }
            ulonglong2* dst = (ulonglong2*)&g_pyd[h * NS + n0 + ty * 4];
            dst[0] = make_ulonglong2(vals[0], vals[1]);
            dst[1] = make_ulonglong2(vals[2], vals[3]);
        }
    }
}

// ---------------------------------------------------------------------------
// Kernel 2: split-k pairwise partial. grid (16,16,SPLIT) = 512 blocks, 256 thr.
// Tile 64 i x 64 j over KHALF=128 k, micro 4i x 4j (16 products/thread).
// 4096 warps (~27/SM): warp supply of R8 + micro-tile (LDS/product) of R7.
// No exp, no diag, no atomics here — just write partial T1 (f32x2 pairs).
// ---------------------------------------------------------------------------
__global__ void __launch_bounds__(256)
pairwise_partial(void) {
    __shared__ u64   Ys[2][32][64];   // [buf][k][i]  (v,v) pairs  32KB
    __shared__ float Xs[2][32][64];   // [buf][k][j]               16KB
    __shared__ u64   w2s[KHALF];      //                            1KB

    const int t  = threadIdx.x;        // 0..255
    const int gi = t >> 4;             // 0..15
    const int gj = t & 15;             // 0..15
    const int bi = blockIdx.y * 64;
    const int bj = blockIdx.x * 64;
    const int s  = blockIdx.z;
    const int k0 = s * KHALF;

    if (t < KHALF) w2s[t] = g_w2p[k0 + t];

    auto load_stage = [&](int buf, int kk) {
        // Ys: 32k x 64i u64 = 1024 x 16B; 4 per thread.
#pragma unroll
        for (int q = 0; q < 4; q++) {
            int f  = t + q * 256;
            int k  = f >> 5;                 // 0..31
            int c2 = (f & 31) * 2;
            cpa16(&Ys[buf][k][c2], &g_pyd[(k0 + kk + k) * NS + bi + c2]);
        }
        // Xs: 32k x 64j float = 512 x 16B; 2 per thread.
#pragma unroll
        for (int q = 0; q < 2; q++) {
            int f  = t + q * 256;
            int k  = f >> 4;                 // 0..31
            int c4 = (f & 15) * 4;
            cpa16(&Xs[buf][k][c4], &g_px_t[(k0 + kk + k) * NS + bj + c4]);
        }
        cpa_commit();
    };

    u64 acc[4][2];
#pragma unroll
    for (int a = 0; a < 4; a++) { acc[a][0] = 0ull; acc[a][1] = 0ull; }

    load_stage(0, 0);

    const int NCHUNK = KHALF / 32;     // 4
    for (int it = 0; it < NCHUNK; it++) {
        const int cur = it & 1;
        if (it + 1 < NCHUNK) {
            load_stage(cur ^ 1, (it + 1) * 32);
            cpa_wait<1>();
        } else {
            cpa_wait<0>();
        }
        __syncthreads();

        const int kk = it * 32;
#pragma unroll 8
        for (int k = 0; k < 32; k++) {
            ulonglong2 ya = *(const ulonglong2*)&Ys[cur][k][gi * 4];
            ulonglong2 yb = *(const ulonglong2*)&Ys[cur][k][gi * 4 + 2];
            ulonglong2 xv = *(const ulonglong2*)&Xs[cur][k][gj * 4];
            u64 w = w2s[kk + k];
            u64 yp[4] = {ya.x, ya.y, yb.x, yb.y};
            u64 xp[2] = {xv.x, xv.y};
#pragma unroll
            for (int a = 0; a < 4; a++)
#pragma unroll
                for (int p = 0; p < 2; p++) {
                    u64 sum = relu2(add2(yp[a], xp[p]));
                    acc[a][p] = fma2(sum, w, acc[a][p]);
                }
        }
        __syncthreads();
    }

    // Write partial tile: row i, 4 consecutive j as one 16B store.
#pragma unroll
    for (int a = 0; a < 4; a++) {
        int i = bi + gi * 4 + a;
        *(ulonglong2*)&g_t1p[s][i * NS + bj + gj * 4] =
            make_ulonglong2(acc[a][0], acc[a][1]);
    }
}

// ---------------------------------------------------------------------------
// Kernel 3: reduce. Add partials, exp-sum, diag-sum, finalize in last block.
// grid 256, block 256; each thread 4 float4 (grid-strided), coalesced.
// ---------------------------------------------------------------------------
__global__ void __launch_bounds__(256)
reduce_kernel(const float* __restrict__ b2, float* __restrict__ out) {
    __shared__ float r1[8], r2[8];
    __shared__ bool  is_last;

    const int t  = threadIdx.x;
    const int tg = blockIdx.x * 256 + t;       // 0..65535
    const float c = b2[0] - 1.0f;

    const float4* P0 = (const float4*)g_t1p[0];
    const float4* P1 = (const float4*)g_t1p[1];

    float sexp = 0.0f, sdiag = 0.0f;

#pragma unroll
    for (int q = 0; q < 4; q++) {
        int fi = tg + q * 65536;               // float4 index, 0..262143
        float4 A = P0[fi];
        float4 B = P1[fi];
        float v0 = A.x + B.x + c;
        float v1 = A.y + B.y + c;
        float v2 = A.z + B.z + c;
        float v3 = A.w + B.w + c;
        sexp += __expf(v0) + __expf(v1) + __expf(v2) + __expf(v3);

        int g = fi * 4;
        int i = g >> 10;
        int j = g & 1023;                      // j..j+3 share row i (j % 4 == 0)
        int d = i - j;
        if (d >= 0 && d < 4)
            sdiag += (d == 0) ? v0 : (d == 1) ? v1 : (d == 2) ? v2 : v3;
    }

    const int lane = t & 31, wid = t >> 5;
#pragma unroll
    for (int o = 16; o > 0; o >>= 1) {
        sexp  += __shfl_down_sync(0xFFFFFFFFu, sexp,  o);
        sdiag += __shfl_down_sync(0xFFFFFFFFu, sdiag, o);
    }
    if (lane == 0) { r1[wid] = sexp; r2[wid] = sdiag; }
    __syncthreads();
    if (t == 0) {
        float s1 = 0.0f, s2 = 0.0f;
#pragma unroll
        for (int w = 0; w < 8; w++) { s1 += r1[w]; s2 += r2[w]; }
        atomicAdd(&g_sum_exp,  s1);
        atomicAdd(&g_sum_diag, s2);
        __threadfence();
        unsigned v = atomicAdd(&g_done, 1u);
        is_last = (v == gridDim.x - 1);
    }
    __syncthreads();

    if (is_last && t == 0) {
        g_done = 0;                            // reset for next graph replay
        float n = (float)NS;
        float se = __ldcg(&g_sum_exp);
        float sd = __ldcg(&g_sum_diag);
        out[0] = (sd + n) / n - se / (n * n);
    }
}

// ---------------------------------------------------------------------------
extern "C" void kernel_launch(void* const* d_in, const int* in_sizes, int n_in,
                              void* d_out, int out_size) {
    const float* x  = (const float*)d_in[0];
    const float* y  = (const float*)d_in[1];
    const float* W1 = (const float*)d_in[2];
    const float* b1 = (const float*)d_in[3];
    const float* W2 = (const float*)d_in[4];
    const float* b2 = (const float*)d_in[5];
    float* out = (float*)d_out;

    dim3 blk1(16, 16);
    dim3 g1(HID / 64, NS / 64, 2);
    gemm_pre_kernel<<<g1, blk1>>>(x, y, W1, b1, W2);

    dim3 g2(NS / 64, NS / 64, SPLIT);          // 16 x 16 x 2 = 512 blocks
    pairwise_partial<<<g2, 256>>>();

    reduce_kernel<<<256, 256>>>(b2, out);
}